// round 1
// baseline (speedup 1.0000x reference)
#include <cuda_runtime.h>
#include <math.h>

// ---- problem geometry (sized generously; actual sizes come from in_sizes) ----
#define KS      20        // gaussian kernel size
#define MAX_W   4096
#define MAX_A   256
#define MAX_L   64
#define MAX_NP  512

// ---- device scratch (no allocations allowed) ----
__device__ float g_n_unk_w[MAX_W];            // unknown-layer n sampled at each wavelength
__device__ float g_inv_lam[MAX_W];            // 1/lambda
__device__ float g_s2[MAX_A];                 // (n0 * sin(angle))^2  (Snell invariant squared)
__device__ float g_q[MAX_L * MAX_A];          // q_j(a) = sqrt(n_j^2 - s2), fixed layers
__device__ float g_r[MAX_L * MAX_A];          // interface r_k(a), fixed interfaces
__device__ float g_coef[MAX_L * MAX_A];       // 2*pi*d_{k-1}*q_k(a), fixed interior layers
__device__ float g_d_unk_dev;

// ============================================================================
// Prep kernel: single block. Gaussian smoothing of the learnable n curve,
// interpolation onto the simulation wavelengths, and all angle-only tables.
// ============================================================================
__global__ void prep_kernel(const float* __restrict__ nk, int NP,
                            const float* __restrict__ d_unk,
                            const float* __restrict__ th_above, int LA,
                            const float* __restrict__ th_below, int LB,
                            const float* __restrict__ fixed_n,
                            const float* __restrict__ wl, int W,
                            const float* __restrict__ ang, int A)
{
    const int NT = blockDim.x;
    const int t  = threadIdx.x;
    const int L  = LA + LB + 3;     // total layers (incoming + above + unk + below + outgoing)
    const int U  = LA + 1;          // unknown layer index
    const int NS = NP - KS + 1;     // 'valid' conv length

    __shared__ float red[512];
    __shared__ float s_nk[MAX_NP];
    __shared__ float sm_ns[MAX_NP];
    __shared__ float kw[KS];
    __shared__ float s_wmin, s_wmax;

    // ---- min / max of wavelengths ----
    float vmin = 3.0e38f, vmax = -3.0e38f;
    for (int i = t; i < W; i += NT) {
        float x = wl[i];
        vmin = fminf(vmin, x);
        vmax = fmaxf(vmax, x);
    }
    red[t] = vmin; __syncthreads();
    for (int o = NT >> 1; o > 0; o >>= 1) { if (t < o) red[t] = fminf(red[t], red[t + o]); __syncthreads(); }
    if (t == 0) s_wmin = red[0];
    __syncthreads();
    red[t] = vmax; __syncthreads();
    for (int o = NT >> 1; o > 0; o >>= 1) { if (t < o) red[t] = fmaxf(red[t], red[t + o]); __syncthreads(); }
    if (t == 0) s_wmax = red[0];

    // ---- gaussian kernel weights (AMPLITUDE cancels in normalization) ----
    if (t < KS) {
        float x = -10.0f + 20.0f * (float)t / (float)(KS - 1);
        kw[t] = expf(-(x * x) / (2.0f * 4.0f * 4.0f));   // sigma = 4
    }
    // stage the learnable n curve
    for (int i = t; i < NP; i += NT) s_nk[i] = nk[i];
    __syncthreads();
    if (t == 0) {
        float s = 0.f;
        for (int i = 0; i < KS; ++i) s += kw[i];
        float inv = 1.0f / s;
        for (int i = 0; i < KS; ++i) kw[i] *= inv;
        g_d_unk_dev = d_unk[0];
    }
    __syncthreads();

    // ---- 'valid' convolution (kernel is symmetric -> no flip needed) ----
    for (int i = t; i < NS; i += NT) {
        float acc = 0.f;
        #pragma unroll
        for (int k = 0; k < KS; ++k) acc += s_nk[i + k] * kw[k];
        sm_ns[i] = acc;
    }
    __syncthreads();

    // ---- interp onto simulation wavelengths (uniform dyn_wl grid) ----
    const float wmin = s_wmin, wmax = s_wmax;
    const float invh = (float)(NS - 1) / (wmax - wmin);
    for (int w = t; w < W; w += NT) {
        float lam = wl[w];
        float tp  = (lam - wmin) * invh;
        tp = fminf(fmaxf(tp, 0.f), (float)(NS - 1));
        int i0 = min((int)tp, NS - 2);
        float f = tp - (float)i0;
        g_n_unk_w[w] = sm_ns[i0] + f * (sm_ns[i0 + 1] - sm_ns[i0]);
        g_inv_lam[w] = 1.0f / lam;
    }

    // ---- angle-only tables ----
    const float n0     = fixed_n[0];
    const float TWO_PI = 6.283185307179586f;
    for (int a = t; a < A; a += NT) {
        float sa = sinf(ang[a]);
        float s  = n0 * sa;
        float s2 = s * s;
        g_s2[a] = s2;
        for (int j = 0; j < L; ++j) {
            float q = 0.f;
            if (j != U) {
                float nj = fixed_n[j < U ? j : j - 1];
                q = sqrtf(fmaxf(nj * nj - s2, 0.f));
            }
            g_q[j * MAX_A + a] = q;
        }
        // interface r_k(a); interfaces touching the unknown layer done per-pixel
        for (int k = 0; k < L - 1; ++k) {
            float r = 0.f;
            if (k != U - 1 && k != U) {
                float qa = g_q[k * MAX_A + a];
                float qb = g_q[(k + 1) * MAX_A + a];
                r = (qa - qb) / (qa + qb);
            }
            g_r[k * MAX_A + a] = r;
        }
        // coef_k(a) = 2*pi * d_{k-1} * q_k(a), interior fixed layers
        for (int k = 1; k < L - 1; ++k) {
            float c = 0.f;
            if (k != U) {
                int   di = k - 1;
                float d  = (di < LA) ? th_above[di] : th_below[di - LA - 1];
                c = TWO_PI * d * g_q[k * MAX_A + a];
            }
            g_coef[k * MAX_A + a] = c;
        }
    }
}

// ============================================================================
// Main TMM kernel: one thread per (wavelength, angle) pixel.
// The 1/t scalings are provably irrelevant to R = |M10/M00|^2 and are dropped.
// ============================================================================
__global__ void tmm_kernel(int W, int A, int LA, int LB, float* __restrict__ out)
{
    const int a = threadIdx.x;
    const int w = blockIdx.x;
    if (a >= A || w >= W) return;
    const int L = LA + LB + 3;
    const int U = LA + 1;

    const float invl = g_inv_lam[w];
    const float s2   = g_s2[a];
    const float nu   = g_n_unk_w[w];
    const float qu   = sqrtf(fmaxf(nu * nu - s2, 0.f));

    // the two wavelength-dependent interfaces (around the unknown layer)
    const float qm = g_q[(U - 1) * MAX_A + a];
    const float qp = g_q[(U + 1) * MAX_A + a];
    const float rA = (qm - qu) / (qm + qu);                   // interface U-1
    const float rB = (qu - qp) / (qu + qp);                   // interface U
    const float coefU = 6.283185307179586f * g_d_unk_dev * qu;

    // M = interface(r0) without the 1/t factor: [[1,r0],[r0,1]]
    const float r0 = g_r[a];
    float m00r = 1.f, m00i = 0.f, m01r = r0, m01i = 0.f;
    float m10r = r0, m10i = 0.f, m11r = 1.f, m11i = 0.f;

    #pragma unroll 8
    for (int k = 1; k < L - 1; ++k) {
        float coef = (k == U) ? coefU : g_coef[k * MAX_A + a];
        float r    = (k == U - 1) ? rA : ((k == U) ? rB : g_r[k * MAX_A + a]);
        float delta = coef * invl;
        float sn, cs;
        sincosf(delta, &sn, &cs);

        // column 0 *= e^{-i d} = (cs, -sn); column 1 *= e^{+i d} = (cs, sn)
        float p00r = m00r * cs + m00i * sn;
        float p00i = m00i * cs - m00r * sn;
        float p10r = m10r * cs + m10i * sn;
        float p10i = m10i * cs - m10r * sn;
        float p01r = m01r * cs - m01i * sn;
        float p01i = m01i * cs + m01r * sn;
        float p11r = m11r * cs - m11i * sn;
        float p11i = m11i * cs + m11r * sn;

        // M = P @ [[1, r],[r, 1]]   (1/t dropped; cancels in M10/M00)
        m00r = p00r + r * p01r;  m00i = p00i + r * p01i;
        m01r = p01r + r * p00r;  m01i = p01i + r * p00i;
        m10r = p10r + r * p11r;  m10i = p10i + r * p11i;
        m11r = p11r + r * p10r;  m11i = p11i + r * p10i;
    }

    float num = m10r * m10r + m10i * m10i;
    float den = m00r * m00r + m00i * m00i;
    out[w * A + a] = num / den;
}

// ============================================================================
extern "C" void kernel_launch(void* const* d_in, const int* in_sizes, int n_in,
                              void* d_out, int out_size)
{
    const float* nk  = (const float*)d_in[0];   // refractive_index [350]
    const float* dun = (const float*)d_in[1];   // unknown_layer_thickness [1]
    const float* ta  = (const float*)d_in[2];   // thickness_above [LA]
    const float* tb  = (const float*)d_in[3];   // thickness_below [LB]
    const float* fn  = (const float*)d_in[4];   // fixed_n [LA+LB+2]
    const float* wl  = (const float*)d_in[5];   // wavelengths [W]
    const float* ang = (const float*)d_in[6];   // angles [A]

    const int NP = in_sizes[0];
    const int LA = in_sizes[2];
    const int LB = in_sizes[3];
    const int W  = in_sizes[5];
    const int A  = in_sizes[6];
    float* out = (float*)d_out;

    prep_kernel<<<1, 512>>>(nk, NP, dun, ta, LA, tb, LB, fn, wl, W, ang, A);
    tmm_kernel<<<W, A>>>(W, A, LA, LB, out);
}

// round 2
// speedup vs baseline: 1.6064x; 1.6064x over previous
#include <cuda_runtime.h>
#include <math.h>

// ---- problem geometry (sized generously; actual sizes come from in_sizes) ----
#define KS      20        // gaussian kernel size
#define MAX_W   4096
#define MAX_A   256
#define MAX_L   64
#define MAX_NP  512

// ---- device scratch (no allocations allowed) ----
__device__ float  g_n_unk_w[MAX_W];           // unknown-layer n sampled at each wavelength
__device__ float  g_inv_lam[MAX_W];           // 1/lambda
__device__ float  g_s2[MAX_A];                // (n0 * sin(angle))^2
__device__ float  g_r0[MAX_A];                // first interface r
__device__ float  g_qm[MAX_A];                // q_{U-1}(a)
__device__ float  g_qp[MAX_A];                // q_{U+1}(a)
__device__ float2 g_cr[MAX_L * MAX_A];        // (coef_k, r_k) for interior steps
__device__ float  g_d_unk_dev;

// ============================================================================
// Prep kernel: single block. Gaussian smoothing, wavelength interp, and all
// angle-only tables packed as float2 (coef, r) per interior step.
// ============================================================================
__global__ void prep_kernel(const float* __restrict__ nk, int NP,
                            const float* __restrict__ d_unk,
                            const float* __restrict__ th_above, int LA,
                            const float* __restrict__ th_below, int LB,
                            const float* __restrict__ fixed_n,
                            const float* __restrict__ wl, int W,
                            const float* __restrict__ ang, int A)
{
    const int NT = blockDim.x;
    const int t  = threadIdx.x;
    const int L  = LA + LB + 3;     // total layers
    const int U  = LA + 1;          // unknown layer index
    const int NS = NP - KS + 1;     // 'valid' conv length

    __shared__ float red[512];
    __shared__ float s_nk[MAX_NP];
    __shared__ float sm_ns[MAX_NP];
    __shared__ float kw[KS];
    __shared__ float s_wmin, s_wmax;
    __shared__ float s_q[MAX_L];    // scratch per-angle is NOT shared; this is per fixed layer n^2
    __shared__ float s_n2[MAX_L];
    __shared__ float s_d[MAX_L];

    // ---- min / max of wavelengths ----
    float vmin = 3.0e38f, vmax = -3.0e38f;
    for (int i = t; i < W; i += NT) {
        float x = wl[i];
        vmin = fminf(vmin, x);
        vmax = fmaxf(vmax, x);
    }
    red[t] = vmin; __syncthreads();
    for (int o = NT >> 1; o > 0; o >>= 1) { if (t < o) red[t] = fminf(red[t], red[t + o]); __syncthreads(); }
    if (t == 0) s_wmin = red[0];
    __syncthreads();
    red[t] = vmax; __syncthreads();
    for (int o = NT >> 1; o > 0; o >>= 1) { if (t < o) red[t] = fmaxf(red[t], red[t + o]); __syncthreads(); }
    if (t == 0) s_wmax = red[0];

    // ---- gaussian kernel weights ----
    if (t < KS) {
        float x = -10.0f + 20.0f * (float)t / (float)(KS - 1);
        kw[t] = expf(-(x * x) / (2.0f * 4.0f * 4.0f));   // sigma = 4
    }
    for (int i = t; i < NP; i += NT) s_nk[i] = nk[i];
    // stage fixed n^2 and thicknesses (layer-indexed, unknown slot skipped)
    if (t < L) {
        float nj = (t == U) ? 0.f : fixed_n[t < U ? t : t - 1];
        s_n2[t] = nj * nj;
    }
    if (t >= 1 && t < L - 1) {
        int di = t - 1;
        s_d[t] = (t == U) ? 0.f : ((di < LA) ? th_above[di] : th_below[di - LA - 1]);
    }
    __syncthreads();
    if (t == 0) {
        float s = 0.f;
        for (int i = 0; i < KS; ++i) s += kw[i];
        float inv = 1.0f / s;
        for (int i = 0; i < KS; ++i) kw[i] *= inv;
        g_d_unk_dev = d_unk[0];
    }
    __syncthreads();

    // ---- 'valid' convolution (symmetric kernel -> no flip) ----
    for (int i = t; i < NS; i += NT) {
        float acc = 0.f;
        #pragma unroll
        for (int k = 0; k < KS; ++k) acc += s_nk[i + k] * kw[k];
        sm_ns[i] = acc;
    }
    __syncthreads();

    // ---- interp onto simulation wavelengths (uniform dyn_wl grid) ----
    const float wmin = s_wmin, wmax = s_wmax;
    const float invh = (float)(NS - 1) / (wmax - wmin);
    for (int w = t; w < W; w += NT) {
        float lam = wl[w];
        float tp  = (lam - wmin) * invh;
        tp = fminf(fmaxf(tp, 0.f), (float)(NS - 1));
        int i0 = min((int)tp, NS - 2);
        float f = tp - (float)i0;
        g_n_unk_w[w] = sm_ns[i0] + f * (sm_ns[i0 + 1] - sm_ns[i0]);
        g_inv_lam[w] = 1.0f / lam;
    }

    // ---- angle-only tables ----
    const float n0     = fixed_n[0];
    const float TWO_PI = 6.283185307179586f;
    for (int a = t; a < A; a += NT) {
        float sa = sinf(ang[a]);
        float s  = n0 * sa;
        float s2 = s * s;
        g_s2[a] = s2;

        float q[MAX_L];
        for (int j = 0; j < L; ++j)
            q[j] = (j == U) ? 0.f : sqrtf(fmaxf(s_n2[j] - s2, 0.f));
        g_qm[a] = q[U - 1];
        g_qp[a] = q[U + 1];
        g_r0[a] = (q[0] - q[1]) / (q[0] + q[1]);

        // per-step (coef_k, r_k): layer-k phase coef and interface-k r
        for (int k = 1; k < L - 1; ++k) {
            float coef = (k == U) ? 0.f : TWO_PI * s_d[k] * q[k];
            float r    = 0.f;
            if (k != U - 1 && k != U)
                r = (q[k] - q[k + 1]) / (q[k] + q[k + 1]);
            g_cr[k * MAX_A + a] = make_float2(coef, r);
        }
    }
}

// ============================================================================
// Main TMM kernel: one thread per (wavelength, angle) pixel.
// Lossless symmetry: M = [[A,B],[conj(B),conj(A)]], so only A,B are carried.
// R = |B|^2 / |A|^2.  (1/t factors cancel and are dropped.)
// ============================================================================
__device__ __forceinline__ void tmm_step(float& Ar, float& Ai, float& Br, float& Bi,
                                         float coef, float r, float invl)
{
    float sn, cs;
    __sincosf(coef * invl, &sn, &cs);
    // ea = A * e^{-i d};  eb = B * e^{+i d}
    float ear = fmaf(Ar, cs,  Ai * sn);
    float eai = fmaf(Ai, cs, -Ar * sn);
    float ebr = fmaf(Br, cs, -Bi * sn);
    float ebi = fmaf(Bi, cs,  Br * sn);
    // A' = ea + r*eb ; B' = r*ea + eb
    Ar = fmaf(r, ebr, ear);
    Ai = fmaf(r, ebi, eai);
    Br = fmaf(r, ear, ebr);
    Bi = fmaf(r, eai, ebi);
}

__global__ void tmm_kernel(int W, int A, int LA, int LB, float* __restrict__ out)
{
    const int a = threadIdx.x;
    const int w = blockIdx.x;
    if (a >= A) return;
    const int L = LA + LB + 3;
    const int U = LA + 1;

    const float invl = g_inv_lam[w];
    const float s2   = g_s2[a];
    const float nu   = g_n_unk_w[w];
    const float qu   = sqrtf(fmaxf(nu * nu - s2, 0.f));

    const float qm = g_qm[a];
    const float qp = g_qp[a];
    const float rA = (qm - qu) / (qm + qu);           // interface U-1
    const float rB = (qu - qp) / (qu + qp);           // interface U
    const float deltaU = 6.283185307179586f * g_d_unk_dev * qu * invl;

    const float r0 = g_r0[a];
    float Ar = 1.f, Ai = 0.f, Br = r0, Bi = 0.f;

    const float2* cr = &g_cr[a];

    // k = 1 .. U-2 : pure table
    #pragma unroll 7
    for (int k = 1; k < U - 1; ++k) {
        float2 c = cr[k * MAX_A];
        tmm_step(Ar, Ai, Br, Bi, c.x, c.y, invl);
    }
    // k = U-1 : table coef, per-pixel rA
    {
        float2 c = cr[(U - 1) * MAX_A];
        tmm_step(Ar, Ai, Br, Bi, c.x, rA, invl);
    }
    // k = U : unknown layer (per-pixel phase & rB)
    {
        float sn, cs;
        __sincosf(deltaU, &sn, &cs);
        float ear = fmaf(Ar, cs,  Ai * sn);
        float eai = fmaf(Ai, cs, -Ar * sn);
        float ebr = fmaf(Br, cs, -Bi * sn);
        float ebi = fmaf(Bi, cs,  Br * sn);
        Ar = fmaf(rB, ebr, ear);
        Ai = fmaf(rB, ebi, eai);
        Br = fmaf(rB, ear, ebr);
        Bi = fmaf(rB, eai, ebi);
    }
    // k = U+1 .. L-2 : pure table
    #pragma unroll 8
    for (int k = U + 1; k < L - 1; ++k) {
        float2 c = cr[k * MAX_A];
        tmm_step(Ar, Ai, Br, Bi, c.x, c.y, invl);
    }

    float num = fmaf(Br, Br, Bi * Bi);
    float den = fmaf(Ar, Ar, Ai * Ai);
    out[w * A + a] = num / den;
}

// ============================================================================
extern "C" void kernel_launch(void* const* d_in, const int* in_sizes, int n_in,
                              void* d_out, int out_size)
{
    const float* nk  = (const float*)d_in[0];   // refractive_index [350]
    const float* dun = (const float*)d_in[1];   // unknown_layer_thickness [1]
    const float* ta  = (const float*)d_in[2];   // thickness_above [LA]
    const float* tb  = (const float*)d_in[3];   // thickness_below [LB]
    const float* fn  = (const float*)d_in[4];   // fixed_n [LA+LB+2]
    const float* wl  = (const float*)d_in[5];   // wavelengths [W]
    const float* ang = (const float*)d_in[6];   // angles [A]

    const int NP = in_sizes[0];
    const int LA = in_sizes[2];
    const int LB = in_sizes[3];
    const int W  = in_sizes[5];
    const int A  = in_sizes[6];
    float* out = (float*)d_out;

    prep_kernel<<<1, 512>>>(nk, NP, dun, ta, LA, tb, LB, fn, wl, W, ang, A);
    tmm_kernel<<<W, A>>>(W, A, LA, LB, out);
}

// round 6
// speedup vs baseline: 2.8309x; 1.7623x over previous
#include <cuda_runtime.h>
#include <math.h>

// ---- problem geometry (sized generously; actual sizes come from in_sizes) ----
#define KS      20        // gaussian kernel size
#define MAX_W   4096
#define MAX_A   256
#define MAX_L   64

#define FOUR_PI 12.566370614359172f

// ---- device scratch (no allocations allowed) ----
__device__ float  g_n_unk_w[MAX_W];           // unknown-layer n at each wavelength
__device__ float  g_inv_lam[MAX_W];           // 1/lambda
__device__ float  g_s2[MAX_A];                // (n0 * sin(angle))^2
__device__ float  g_r0[MAX_A];                // first interface r
__device__ float  g_qm[MAX_A];                // q_{U-1}(a)
__device__ float  g_qp[MAX_A];                // q_{U+1}(a)
__device__ float2 g_cr[MAX_L * MAX_A];        // (coef2_k = 4*pi*d_k*q_k, r_k)
__device__ float  g_d_unk_dev;

// ============================================================================
// Prep kernel: 16 blocks x 256 threads.
//   blocks 0..7 : wavelength job (min/max, gaussian conv on the fly, interp)
//   blocks 8..15: angle tables, one task per (layer k, angle a)
// ============================================================================
__global__ void prep_kernel(const float* __restrict__ nk, int NP,
                            const float* __restrict__ d_unk,
                            const float* __restrict__ ta, int LA,
                            const float* __restrict__ tb, int LB,
                            const float* __restrict__ fn,
                            const float* __restrict__ wl, int W,
                            const float* __restrict__ ang, int A)
{
    const int bid = blockIdx.x, tid = threadIdx.x;
    const int L = LA + LB + 3;
    const int U = LA + 1;

    if (bid < 8) {
        // ---- wavelength job ----
        __shared__ float rmin[256], rmax[256];
        float vmin = 3.0e38f, vmax = -3.0e38f;
        for (int i = tid; i < W; i += 256) {
            float x = wl[i];
            vmin = fminf(vmin, x);
            vmax = fmaxf(vmax, x);
        }
        rmin[tid] = vmin; rmax[tid] = vmax; __syncthreads();
        for (int o = 128; o > 0; o >>= 1) {
            if (tid < o) {
                rmin[tid] = fminf(rmin[tid], rmin[tid + o]);
                rmax[tid] = fmaxf(rmax[tid], rmax[tid + o]);
            }
            __syncthreads();
        }
        const float wmin = rmin[0], wmax = rmax[0];

        // gaussian weights in registers (AMPLITUDE cancels in normalization)
        float kw[KS]; float s = 0.f;
        #pragma unroll
        for (int i = 0; i < KS; ++i) {
            float x = -10.f + (20.f / 19.f) * (float)i;
            kw[i] = expf(-x * x * (1.f / 32.f));       // sigma = 4
            s += kw[i];
        }
        float inv = 1.f / s;
        #pragma unroll
        for (int i = 0; i < KS; ++i) kw[i] *= inv;

        const int NS = NP - KS + 1;
        const float invh = (float)(NS - 1) / (wmax - wmin);
        for (int w = bid * 256 + tid; w < W; w += 8 * 256) {
            float lam = wl[w];
            float tp = fminf(fmaxf((lam - wmin) * invh, 0.f), (float)(NS - 1));
            int i0 = min((int)tp, NS - 2);
            float f = tp - (float)i0;
            float a0 = 0.f, a1 = 0.f;
            #pragma unroll
            for (int j = 0; j < KS; ++j) a0 = fmaf(nk[i0 + j], kw[j], a0);
            #pragma unroll
            for (int j = 0; j < KS; ++j) a1 = fmaf(nk[i0 + 1 + j], kw[j], a1);
            g_n_unk_w[w] = a0 + f * (a1 - a0);
            g_inv_lam[w] = 1.0f / lam;
        }
        if (bid == 0 && tid == 0) g_d_unk_dev = d_unk[0];
    } else {
        // ---- angle-table job: task = (k in 1..L-2) x (a in 0..A-1) ----
        const float n0 = fn[0];
        const int ntask = (L - 2) * A;
        for (int idx = (bid - 8) * 256 + tid; idx < ntask; idx += 8 * 256) {
            int k = 1 + idx / A;
            int a = idx - (k - 1) * A;
            float sa = sinf(ang[a]);
            float sv = n0 * sa;
            float s2 = sv * sv;

            // q of fixed layer j (j != U)
            #define QOF(j) sqrtf(fmaxf(fn[(j) < U ? (j) : (j) - 1] * fn[(j) < U ? (j) : (j) - 1] - s2, 0.f))

            float coef2 = 0.f, r = 0.f;
            if (k != U) {
                int di = k - 1;
                float d = (di < LA) ? ta[di] : tb[di - LA - 1];
                float qk = QOF(k);
                coef2 = FOUR_PI * d * qk;              // 2*delta coefficient
                if (k != U - 1) {
                    float qn = QOF(k + 1);
                    r = (qk - qn) / (qk + qn);
                }
            }
            g_cr[k * MAX_A + a] = make_float2(coef2, r);

            if (k == 1) {
                g_s2[a] = s2;
                float q0 = QOF(0), q1 = QOF(1);
                g_r0[a] = (q0 - q1) / (q0 + q1);
            }
            if (k == U - 1) g_qm[a] = QOF(U - 1);
            if (k == U + 1) g_qp[a] = QOF(U + 1);
            #undef QOF
        }
    }
}

// ============================================================================
// TMM step with global phase factored out:
//   t  = A * e^{-2i delta}
//   A' = t + r*B ; B' = r*t + B       (global phase cancels in R = |B|^2/|A|^2)
// ============================================================================
__device__ __forceinline__ void tmm_step(float& Ar, float& Ai, float& Br, float& Bi,
                                         float ang2, float r)
{
    float sn, cs;
    __sincosf(ang2, &sn, &cs);
    float tr = fmaf(Ar, cs,  Ai * sn);
    float ti = fmaf(Ai, cs, -Ar * sn);
    float nAr = fmaf(r, Br, tr);
    float nAi = fmaf(r, Bi, ti);
    Br = fmaf(r, tr, Br);
    Bi = fmaf(r, ti, Bi);
    Ar = nAr; Ai = nAi;
}

// ============================================================================
// Specialized main kernel: 2 wavelengths per thread, fully unrolled.
// ============================================================================
template<int LAc, int LBc>
__global__ void __launch_bounds__(128, 7)
tmm_kernel_t(int W, int A, float* __restrict__ out)
{
    constexpr int L = LAc + LBc + 3;
    constexpr int U = LAc + 1;
    const int a = threadIdx.x;
    const int w0 = blockIdx.x * 2;
    const int w1 = w0 + 1;
    const bool has1 = (w1 < W);
    const int w1c = has1 ? w1 : w0;

    const float invl0 = g_inv_lam[w0];
    const float invl1 = g_inv_lam[w1c];
    const float s2 = g_s2[a];
    const float qm = g_qm[a];
    const float qp = g_qp[a];
    const float du = g_d_unk_dev;

    const float nu0 = g_n_unk_w[w0];
    const float nu1 = g_n_unk_w[w1c];
    const float qu0 = sqrtf(fmaxf(fmaf(nu0, nu0, -s2), 0.f));
    const float qu1 = sqrtf(fmaxf(fmaf(nu1, nu1, -s2), 0.f));
    const float rA0 = (qm - qu0) / (qm + qu0);
    const float rA1 = (qm - qu1) / (qm + qu1);
    const float rB0 = (qu0 - qp) / (qu0 + qp);
    const float rB1 = (qu1 - qp) / (qu1 + qp);
    const float dU0 = FOUR_PI * du * qu0 * invl0;     // 2*delta_unknown
    const float dU1 = FOUR_PI * du * qu1 * invl1;

    const float r0 = g_r0[a];
    float A0r = 1.f, A0i = 0.f, B0r = r0, B0i = 0.f;
    float A1r = 1.f, A1i = 0.f, B1r = r0, B1i = 0.f;

    #pragma unroll
    for (int k = 1; k <= L - 2; ++k) {
        if (k == U) {
            tmm_step(A0r, A0i, B0r, B0i, dU0, rB0);
            tmm_step(A1r, A1i, B1r, B1i, dU1, rB1);
        } else {
            float2 c = g_cr[k * MAX_A + a];
            if (k == U - 1) {
                tmm_step(A0r, A0i, B0r, B0i, c.x * invl0, rA0);
                tmm_step(A1r, A1i, B1r, B1i, c.x * invl1, rA1);
            } else {
                tmm_step(A0r, A0i, B0r, B0i, c.x * invl0, c.y);
                tmm_step(A1r, A1i, B1r, B1i, c.x * invl1, c.y);
            }
        }
    }

    out[w0 * A + a] = fmaf(B0r, B0r, B0i * B0i) / fmaf(A0r, A0r, A0i * A0i);
    if (has1)
        out[w1 * A + a] = fmaf(B1r, B1r, B1i * B1i) / fmaf(A1r, A1r, A1i * A1i);
}

// ============================================================================
// Generic fallback: one pixel per thread, runtime loop.
// ============================================================================
__global__ void tmm_kernel_g(int W, int A, int LA, int LB, float* __restrict__ out)
{
    const int a = threadIdx.x;
    const int w = blockIdx.x;
    if (a >= A) return;
    const int L = LA + LB + 3;
    const int U = LA + 1;

    const float invl = g_inv_lam[w];
    const float s2 = g_s2[a];
    const float nu = g_n_unk_w[w];
    const float qu = sqrtf(fmaxf(fmaf(nu, nu, -s2), 0.f));
    const float qm = g_qm[a];
    const float qp = g_qp[a];
    const float rA = (qm - qu) / (qm + qu);
    const float rB = (qu - qp) / (qu + qp);
    const float dU = FOUR_PI * g_d_unk_dev * qu * invl;

    const float r0 = g_r0[a];
    float Ar = 1.f, Ai = 0.f, Br = r0, Bi = 0.f;

    for (int k = 1; k <= L - 2; ++k) {
        float ang2, r;
        if (k == U) { ang2 = dU; r = rB; }
        else {
            float2 c = g_cr[k * MAX_A + a];
            ang2 = c.x * invl;
            r = (k == U - 1) ? rA : c.y;
        }
        tmm_step(Ar, Ai, Br, Bi, ang2, r);
    }
    out[w * A + a] = fmaf(Br, Br, Bi * Bi) / fmaf(Ar, Ar, Ai * Ai);
}

// ============================================================================
extern "C" void kernel_launch(void* const* d_in, const int* in_sizes, int n_in,
                              void* d_out, int out_size)
{
    const float* nk  = (const float*)d_in[0];   // refractive_index [NP]
    const float* dun = (const float*)d_in[1];   // unknown_layer_thickness [1]
    const float* ta  = (const float*)d_in[2];   // thickness_above [LA]
    const float* tb  = (const float*)d_in[3];   // thickness_below [LB]
    const float* fn  = (const float*)d_in[4];   // fixed_n [LA+LB+2]
    const float* wl  = (const float*)d_in[5];   // wavelengths [W]
    const float* ang = (const float*)d_in[6];   // angles [A]

    const int NP = in_sizes[0];
    const int LA = in_sizes[2];
    const int LB = in_sizes[3];
    const int W  = in_sizes[5];
    const int A  = in_sizes[6];
    float* out = (float*)d_out;

    prep_kernel<<<16, 256>>>(nk, NP, dun, ta, LA, tb, LB, fn, wl, W, ang, A);

    if (LA == 15 && LB == 15) {
        tmm_kernel_t<15, 15><<<(W + 1) / 2, A>>>(W, A, out);
    } else {
        tmm_kernel_g<<<W, A>>>(W, A, LA, LB, out);
    }
}